// round 4
// baseline (speedup 1.0000x reference)
#include <cuda_runtime.h>
#include <math_constants.h>

#define BB 2
#define NN 4096
#define DD 128

// Scratch (allocation-free rule: __device__ globals)
__device__ __align__(16) float g_ul[DD];
__device__ __align__(16) float g_ur[DD];
__device__ __align__(16) float g_l[BB * NN];
__device__ __align__(16) float g_r[BB * NN];

// ---------------------------------------------------------------------------
// Kernel 0: fold Wa into two vectors.  u_l[d] = sum_e Wa[e,d] * w_l[e]
// One block, 128 threads. Coalesced reads of Wa rows; w_l/w_r broadcast.
// ---------------------------------------------------------------------------
__global__ void k_fold(const float* __restrict__ Wa,
                       const float* __restrict__ wl,
                       const float* __restrict__ wr) {
    int d = threadIdx.x;
    float sl = 0.f, sr = 0.f;
#pragma unroll 8
    for (int e = 0; e < DD; ++e) {
        float a = Wa[e * DD + d];
        sl = fmaf(a, wl[e], sl);
        sr = fmaf(a, wr[e], sr);
    }
    g_ul[d] = sl;
    g_ur[d] = sr;
}

// ---------------------------------------------------------------------------
// Kernel 1: per-token scalars. One warp per token; lane holds 4 dims (float4).
// demands -> d_out[0:B*N] (sigmoid), l/r -> scratch.
// ---------------------------------------------------------------------------
__global__ void __launch_bounds__(256)
k_token(const float* __restrict__ x,
        const float* __restrict__ Wd,
        const float* __restrict__ bd,
        float* __restrict__ demands) {
    int gwarp = (blockIdx.x * blockDim.x + threadIdx.x) >> 5;
    int lane  = threadIdx.x & 31;
    if (gwarp >= BB * NN) return;

    const float4* xr = reinterpret_cast<const float4*>(x + (size_t)gwarp * DD);
    float4 v  = xr[lane];
    float4 wd = reinterpret_cast<const float4*>(Wd)[lane];
    float4 ul = reinterpret_cast<const float4*>(g_ul)[lane];
    float4 ur = reinterpret_cast<const float4*>(g_ur)[lane];

    float sd = v.x * wd.x + v.y * wd.y + v.z * wd.z + v.w * wd.w;
    float sl = v.x * ul.x + v.y * ul.y + v.z * ul.z + v.w * ul.w;
    float sr = v.x * ur.x + v.y * ur.y + v.z * ur.z + v.w * ur.w;

#pragma unroll
    for (int o = 16; o > 0; o >>= 1) {
        sd += __shfl_xor_sync(0xFFFFFFFFu, sd, o);
        sl += __shfl_xor_sync(0xFFFFFFFFu, sl, o);
        sr += __shfl_xor_sync(0xFFFFFFFFu, sr, o);
    }
    if (lane == 0) {
        demands[gwarp] = 1.0f / (1.0f + expf(-(sd + bd[0])));
        g_l[gwarp] = sl;
        g_r[gwarp] = sr;
    }
}

// ---------------------------------------------------------------------------
// Kernel 2: row softmax + scale.  block = one row i of batch b.
// Each thread keeps 16 elements (4 x float4) in registers through
// max -> exp -> sum -> scaled write. r[] is L2-resident (16 KB/batch).
// Streaming stores (__stcs): 134 MB output, never re-read.
// ---------------------------------------------------------------------------
__global__ void __launch_bounds__(256)
k_softmax(float* __restrict__ gs, const float* __restrict__ demands) {
    const int i   = blockIdx.x;
    const int b   = blockIdx.y;
    const int tid = threadIdx.x;
    const int row = b * NN + i;

    const float li  = g_l[row];
    const float dem = demands[row];
    const float4* r4 = reinterpret_cast<const float4*>(g_r + b * NN);

    float4 f[4];
    float lmax = -CUDART_INF_F;
#pragma unroll
    for (int k = 0; k < 4; ++k) {
        float4 rv = __ldg(&r4[tid + k * 256]);
        float4 t;
        t.x = li + rv.x; t.y = li + rv.y; t.z = li + rv.z; t.w = li + rv.w;
        t.x = (t.x > 0.f) ? t.x : 0.01f * t.x;
        t.y = (t.y > 0.f) ? t.y : 0.01f * t.y;
        t.z = (t.z > 0.f) ? t.z : 0.01f * t.z;
        t.w = (t.w > 0.f) ? t.w : 0.01f * t.w;
        f[k] = t;
        lmax = fmaxf(lmax, fmaxf(fmaxf(t.x, t.y), fmaxf(t.z, t.w)));
    }

    __shared__ float smax[8];
    __shared__ float ssum[8];

    // block max
#pragma unroll
    for (int o = 16; o > 0; o >>= 1)
        lmax = fmaxf(lmax, __shfl_xor_sync(0xFFFFFFFFu, lmax, o));
    if ((tid & 31) == 0) smax[tid >> 5] = lmax;
    __syncthreads();
    float m = smax[0];
#pragma unroll
    for (int w = 1; w < 8; ++w) m = fmaxf(m, smax[w]);

    // exp + local sum (values stay in registers)
    float lsum = 0.f;
#pragma unroll
    for (int k = 0; k < 4; ++k) {
        f[k].x = __expf(f[k].x - m);
        f[k].y = __expf(f[k].y - m);
        f[k].z = __expf(f[k].z - m);
        f[k].w = __expf(f[k].w - m);
        lsum += (f[k].x + f[k].y) + (f[k].z + f[k].w);
    }
#pragma unroll
    for (int o = 16; o > 0; o >>= 1)
        lsum += __shfl_xor_sync(0xFFFFFFFFu, lsum, o);
    if ((tid & 31) == 0) ssum[tid >> 5] = lsum;
    __syncthreads();
    float tot = 0.f;
#pragma unroll
    for (int w = 0; w < 8; ++w) tot += ssum[w];

    const float scale = dem / tot;
    float4* out4 = reinterpret_cast<float4*>(gs + (size_t)row * NN);
#pragma unroll
    for (int k = 0; k < 4; ++k) {
        float4 o;
        o.x = f[k].x * scale; o.y = f[k].y * scale;
        o.z = f[k].z * scale; o.w = f[k].w * scale;
        __stcs(&out4[tid + k * 256], o);
    }
}

// ---------------------------------------------------------------------------
// Launch. Inputs (metadata order):
//   0: embed_feat [B,N,D] f32   1: predict_G int32 (==1 in this dataset)
//   2: W_demand [D]             3: b_demand [1]
//   4: Wa [D,D]                 5: w_l [D]     6: w_r [D]
// Output: demands [B*N] floats, then Gs [B*N*N] floats.
// ---------------------------------------------------------------------------
extern "C" void kernel_launch(void* const* d_in, const int* in_sizes, int n_in,
                              void* d_out, int out_size) {
    const float* x  = (const float*)d_in[0];
    const float* Wd = (const float*)d_in[2];
    const float* bd = (const float*)d_in[3];
    const float* Wa = (const float*)d_in[4];
    const float* wl = (const float*)d_in[5];
    const float* wr = (const float*)d_in[6];

    float* demands = (float*)d_out;
    float* gs      = (float*)d_out + (size_t)BB * NN;

    k_fold<<<1, DD>>>(Wa, wl, wr);

    // 8192 tokens, 1 warp each, 8 warps/block -> 1024 blocks
    k_token<<<(BB * NN * 32) / 256, 256>>>(x, Wd, bd, demands);

    dim3 grid(NN, BB);
    k_softmax<<<grid, 256>>>(gs, demands);
}

// round 5
// speedup vs baseline: 1.1138x; 1.1138x over previous
#include <cuda_runtime.h>
#include <math_constants.h>

#define BB 2
#define NN 4096
#define DD 128

// Scratch (allocation-free rule: __device__ globals)
__device__ __align__(16) float g_ul[DD];
__device__ __align__(16) float g_ur[DD];
__device__ __align__(16) float g_l[BB * NN];
__device__ __align__(16) float g_r[BB * NN];

// ---------------------------------------------------------------------------
// Kernel 0: fold Wa into two vectors.  u_l[d] = sum_e Wa[e,d] * w_l[e]
// v2: 1024 threads = 8 groups x 128 lanes. Group g covers e in [16g, 16g+16)
// with a fully unrolled 16-deep independent load chain (MLP=16/thread,
// 32 warps) -> one exposed DRAM latency instead of ~16. smem tree-reduce.
// ---------------------------------------------------------------------------
__global__ void __launch_bounds__(1024)
k_fold(const float* __restrict__ Wa,
       const float* __restrict__ wl,
       const float* __restrict__ wr) {
    __shared__ float s_sl[8][DD];
    __shared__ float s_sr[8][DD];

    const int d = threadIdx.x & (DD - 1);
    const int g = threadIdx.x >> 7;      // 0..7

    float sl = 0.f, sr = 0.f;
#pragma unroll
    for (int k = 0; k < 16; ++k) {
        const int e = g * 16 + k;
        float a = Wa[e * DD + d];        // coalesced across d; 16 independent per thread
        sl = fmaf(a, wl[e], sl);         // wl[e]/wr[e] broadcast within warp
        sr = fmaf(a, wr[e], sr);
    }
    s_sl[g][d] = sl;
    s_sr[g][d] = sr;
    __syncthreads();

    if (threadIdx.x < DD) {
        float tl = 0.f, tr = 0.f;
#pragma unroll
        for (int j = 0; j < 8; ++j) {    // fixed order -> deterministic
            tl += s_sl[j][d];
            tr += s_sr[j][d];
        }
        g_ul[d] = tl;
        g_ur[d] = tr;
    }
}

// ---------------------------------------------------------------------------
// Kernel 1: per-token scalars. One warp per token; lane holds 4 dims (float4).
// demands -> d_out[0:B*N] (sigmoid), l/r -> scratch.
// ---------------------------------------------------------------------------
__global__ void __launch_bounds__(256)
k_token(const float* __restrict__ x,
        const float* __restrict__ Wd,
        const float* __restrict__ bd,
        float* __restrict__ demands) {
    int gwarp = (blockIdx.x * blockDim.x + threadIdx.x) >> 5;
    int lane  = threadIdx.x & 31;
    if (gwarp >= BB * NN) return;

    const float4* xr = reinterpret_cast<const float4*>(x + (size_t)gwarp * DD);
    float4 v  = xr[lane];
    float4 wd = reinterpret_cast<const float4*>(Wd)[lane];
    float4 ul = reinterpret_cast<const float4*>(g_ul)[lane];
    float4 ur = reinterpret_cast<const float4*>(g_ur)[lane];

    float sd = v.x * wd.x + v.y * wd.y + v.z * wd.z + v.w * wd.w;
    float sl = v.x * ul.x + v.y * ul.y + v.z * ul.z + v.w * ul.w;
    float sr = v.x * ur.x + v.y * ur.y + v.z * ur.z + v.w * ur.w;

#pragma unroll
    for (int o = 16; o > 0; o >>= 1) {
        sd += __shfl_xor_sync(0xFFFFFFFFu, sd, o);
        sl += __shfl_xor_sync(0xFFFFFFFFu, sl, o);
        sr += __shfl_xor_sync(0xFFFFFFFFu, sr, o);
    }
    if (lane == 0) {
        demands[gwarp] = 1.0f / (1.0f + expf(-(sd + bd[0])));
        g_l[gwarp] = sl;
        g_r[gwarp] = sr;
    }
}

// ---------------------------------------------------------------------------
// Kernel 2: row softmax + scale.  block = one row i of batch b.
// Each thread keeps 16 elements (4 x float4) in registers through
// max -> exp -> sum -> scaled write. r[] is L2-resident (16 KB/batch).
// Streaming stores (__stcs): 134 MB output, never re-read.
// ---------------------------------------------------------------------------
__global__ void __launch_bounds__(256)
k_softmax(float* __restrict__ gs, const float* __restrict__ demands) {
    const int i   = blockIdx.x;
    const int b   = blockIdx.y;
    const int tid = threadIdx.x;
    const int row = b * NN + i;

    const float li  = g_l[row];
    const float dem = demands[row];
    const float4* r4 = reinterpret_cast<const float4*>(g_r + b * NN);

    float4 f[4];
    float lmax = -CUDART_INF_F;
#pragma unroll
    for (int k = 0; k < 4; ++k) {
        float4 rv = __ldg(&r4[tid + k * 256]);
        float4 t;
        t.x = li + rv.x; t.y = li + rv.y; t.z = li + rv.z; t.w = li + rv.w;
        t.x = (t.x > 0.f) ? t.x : 0.01f * t.x;
        t.y = (t.y > 0.f) ? t.y : 0.01f * t.y;
        t.z = (t.z > 0.f) ? t.z : 0.01f * t.z;
        t.w = (t.w > 0.f) ? t.w : 0.01f * t.w;
        f[k] = t;
        lmax = fmaxf(lmax, fmaxf(fmaxf(t.x, t.y), fmaxf(t.z, t.w)));
    }

    __shared__ float smax[8];
    __shared__ float ssum[8];

    // block max
#pragma unroll
    for (int o = 16; o > 0; o >>= 1)
        lmax = fmaxf(lmax, __shfl_xor_sync(0xFFFFFFFFu, lmax, o));
    if ((tid & 31) == 0) smax[tid >> 5] = lmax;
    __syncthreads();
    float m = smax[0];
#pragma unroll
    for (int w = 1; w < 8; ++w) m = fmaxf(m, smax[w]);

    // exp + local sum (values stay in registers)
    float lsum = 0.f;
#pragma unroll
    for (int k = 0; k < 4; ++k) {
        f[k].x = __expf(f[k].x - m);
        f[k].y = __expf(f[k].y - m);
        f[k].z = __expf(f[k].z - m);
        f[k].w = __expf(f[k].w - m);
        lsum += (f[k].x + f[k].y) + (f[k].z + f[k].w);
    }
#pragma unroll
    for (int o = 16; o > 0; o >>= 1)
        lsum += __shfl_xor_sync(0xFFFFFFFFu, lsum, o);
    if ((tid & 31) == 0) ssum[tid >> 5] = lsum;
    __syncthreads();
    float tot = 0.f;
#pragma unroll
    for (int w = 0; w < 8; ++w) tot += ssum[w];

    const float scale = dem / tot;
    float4* out4 = reinterpret_cast<float4*>(gs + (size_t)row * NN);
#pragma unroll
    for (int k = 0; k < 4; ++k) {
        float4 o;
        o.x = f[k].x * scale; o.y = f[k].y * scale;
        o.z = f[k].z * scale; o.w = f[k].w * scale;
        __stcs(&out4[tid + k * 256], o);
    }
}

// ---------------------------------------------------------------------------
// Launch. Inputs (metadata order):
//   0: embed_feat [B,N,D] f32   1: predict_G int32 (==1 in this dataset)
//   2: W_demand [D]             3: b_demand [1]
//   4: Wa [D,D]                 5: w_l [D]     6: w_r [D]
// Output: demands [B*N] floats, then Gs [B*N*N] floats.
// ---------------------------------------------------------------------------
extern "C" void kernel_launch(void* const* d_in, const int* in_sizes, int n_in,
                              void* d_out, int out_size) {
    const float* x  = (const float*)d_in[0];
    const float* Wd = (const float*)d_in[2];
    const float* bd = (const float*)d_in[3];
    const float* Wa = (const float*)d_in[4];
    const float* wl = (const float*)d_in[5];
    const float* wr = (const float*)d_in[6];

    float* demands = (float*)d_out;
    float* gs      = (float*)d_out + (size_t)BB * NN;

    k_fold<<<1, 1024>>>(Wa, wl, wr);

    // 8192 tokens, 1 warp each, 8 warps/block -> 1024 blocks
    k_token<<<(BB * NN * 32) / 256, 256>>>(x, Wd, bd, demands);

    dim3 grid(NN, BB);
    k_softmax<<<grid, 256>>>(gs, demands);
}